// round 16
// baseline (speedup 1.0000x reference)
#include <cuda_runtime.h>
#include <cstdint>

#define Hh 384
#define Ww 512
#define Bb 8
#define HW (Hh*Ww)              // 196608
#define NIMG  (Bb*3*HW)         // 4718592
#define NSTEPS 200
#define EBLK 96

// ---------------- static scratch (no allocation allowed) ----------------
__device__ float2 g_flowA[Bb*HW];
__device__ float2 g_flowB[Bb*HW];
__device__ float4 g_imgA[Bb*HW];          // .xyz used
__device__ float4 g_imgB[Bb*HW];
__device__ float4 g_j[Bb*HW];             // j_c = 0.5 - img2p_c  (.xyz used)
__device__ float  g_K[2];                 // K0/2, K1  (pre-divided by H*W)
__device__ float  g_part[2*Bb*EBLK*2];

// ---------------- threefry2x32, JAX-exact, c0 = 0, N independent lanes ----
template<int N>
__device__ __forceinline__ void tf_bitsN(uint32_t k0, uint32_t k1,
                                         const uint32_t* c, uint32_t* r)
{
    const uint32_t ks2 = k0 ^ k1 ^ 0x1BD11BDAu;
    uint32_t x0[N], x1[N];
#pragma unroll
    for (int i = 0; i < N; i++) { x0[i] = k0; x1[i] = c[i] + k1; }

    auto rnd = [&](int rot) {
#pragma unroll
        for (int i = 0; i < N; i++) {
            x0[i] += x1[i];
            x1[i] = __funnelshift_l(x1[i], x1[i], rot);
            x1[i] ^= x0[i];
        }
    };
    auto inj = [&](uint32_t i0, uint32_t i1) {
#pragma unroll
        for (int i = 0; i < N; i++) { x0[i] += i0; x1[i] += i1; }
    };

    rnd(13); rnd(15); rnd(26); rnd(6);  inj(k1,  ks2 + 1u);
    rnd(17); rnd(29); rnd(16); rnd(24); inj(ks2, k0  + 2u);
    rnd(13); rnd(15); rnd(26); rnd(6);  inj(k0,  k1  + 3u);
    rnd(17); rnd(29); rnd(16); rnd(24); inj(k1,  ks2 + 4u);
    rnd(13); rnd(15); rnd(26); rnd(6);  inj(ks2, k0  + 5u);

#pragma unroll
    for (int i = 0; i < N; i++) r[i] = x0[i] ^ x1[i];
}

// ------------- jax.random.normal: uniform(lo,1) -> sqrt(2)*erfinv --------
__device__ __forceinline__ float jax_normal(uint32_t bits)
{
    const float lo = __uint_as_float(0xBF7FFFFFu);      // nextafter(-1, 0)
    float f = __uint_as_float((bits >> 9) | 0x3F800000u) - 1.0f;  // [0,1)
    float u = fmaxf(lo, f * 2.0f + lo);

    float w = -__logf(fmaf(-u, u, 1.0f));
    float p;
    if (w < 5.0f) {
        w = w - 2.5f;
        p =          2.81022636e-08f;
        p = p * w +  3.43273939e-07f;
        p = p * w + -3.5233877e-06f;
        p = p * w + -4.39150654e-06f;
        p = p * w +  0.00021858087f;
        p = p * w + -0.00125372503f;
        p = p * w + -0.00417768164f;
        p = p * w +  0.246640727f;
        p = p * w +  1.50140941f;
    } else {
        w = sqrtf(w) - 3.0f;
        p =         -0.000200214257f;
        p = p * w +  0.000100950558f;
        p = p * w +  0.00134934322f;
        p = p * w + -0.00367342844f;
        p = p * w +  0.00573950773f;
        p = p * w + -0.0076224613f;
        p = p * w +  0.00943887047f;
        p = p * w +  1.00167406f;
        p = p * w +  2.83297682f;
    }
    return 1.41421356237309515f * (p * u);
}

__device__ __forceinline__ float noised_clip(float x, float n)
{
    return fminf(fmaxf(fmaf(0.05f, n, x), -1.0f), 1.0f);
}

// ---------------- one-time prep: K and j ----------------
__global__ void k_init(const float* __restrict__ lw)
{
    g_K[0] = 0.5f * expf(lw[0]) / 196608.0f;   // K0/2
    g_K[1] = expf(lw[1]) / 196608.0f;          // K1 (0.5 and x2 cancel)
}

__global__ void __launch_bounds__(512)
prep_j(const float* __restrict__ input2)
{
    int i = blockIdx.x*512 + threadIdx.x;
    if (i >= NIMG) return;
    int b   = i / (3*HW);
    int r   = i - b*3*HW;
    int c   = r / HW;
    int pix = r - c*HW;
    float i2   = input2[i];
    float i2p  = ((i2*2.0f - 1.0f) + 1.0f) * 0.5f;
    reinterpret_cast<float*>(&g_j[b*HW + pix])[c] = 0.5f - i2p;
}

// ---------------- fused Langevin step: 2 px/thread, 32x32 tile ----------
template<bool SRC_PLANAR>
__global__ void __launch_bounds__(512, 2)
step_kernel(const float* __restrict__ srcp,
            const float2* __restrict__ srcf, const float4* __restrict__ srci,
            float2* __restrict__ dstf, float4* __restrict__ dsti,
            uint32_t k0, uint32_t k1)
{
    __shared__ float2 sft[34][34];         // SCALED (x80) noised flow, 1-halo

    const int b  = blockIdx.z;
    const int h0 = blockIdx.y * 32;
    const int w0 = blockIdx.x * 32;
    const int tid = threadIdx.x;
    const int tx = tid & 15, ty = tid >> 4;     // 16 col-pairs x 32 rows
    const int base_b = b * 5 * HW;

    const int h  = h0 + ty;
    const int c0 = w0 + 2*tx;              // even column; c1 = c0+1
    const int pix0  = h*Ww + c0;
    const int bpix0 = b*HW + pix0;

    // ---- halo duty: ring of 132 cells; ch0 by tid<132, ch1 by tid in [132,264)
    const bool halo0 = (tid < 132);
    const bool halo1 = (tid >= 132) && (tid < 264);
    int hidx = halo0 ? tid : (tid - 132);
    int hh, ww;
    if (hidx < 34)       { hh = -1; ww = hidx - 1; }
    else if (hidx < 68)  { hh = 32; ww = hidx - 35; }
    else if (hidx < 100) { hh = hidx - 68;  ww = -1; }
    else                 { hh = hidx - 100; ww = 32; }
    const int hg = h0 + hh, wg = w0 + ww;
    const bool hval = ((unsigned)hg < (unsigned)Hh) && ((unsigned)wg < (unsigned)Ww);
    const int hpix = hg*Ww + wg;
    const uint32_t hbase = (uint32_t)(base_b + hpix);

    // ---- front-batched loads ----
    float xf0x, xf0y, xf1x, xf1y;
    float xi0[3], xi1[3];
    if (SRC_PLANAR) {
        xf0x = srcp[base_b + pix0];          xf1x = srcp[base_b + pix0 + 1];
        xf0y = srcp[base_b + HW + pix0];     xf1y = srcp[base_b + HW + pix0 + 1];
#pragma unroll
        for (int c = 0; c < 3; c++) {
            xi0[c] = srcp[base_b + (2+c)*HW + pix0];
            xi1[c] = srcp[base_b + (2+c)*HW + pix0 + 1];
        }
    } else {
        float4 vf = *reinterpret_cast<const float4*>(srcf + bpix0);   // bpix0 even
        xf0x = vf.x; xf0y = vf.y; xf1x = vf.z; xf1y = vf.w;
        float4 vi0 = srci[bpix0], vi1 = srci[bpix0+1];
        xi0[0] = vi0.x; xi0[1] = vi0.y; xi0[2] = vi0.z;
        xi1[0] = vi1.x; xi1[1] = vi1.y; xi1[2] = vi1.z;
    }
    float4 j0 = g_j[bpix0], j1 = g_j[bpix0+1];

    float hx = 0.0f;                        // halo src value (ch0 or ch1)
    if ((halo0 || halo1) && hval) {
        if (SRC_PLANAR) hx = srcp[hbase + (halo1 ? HW : 0)];
        else {
            float2 v = srcf[b*HW + hpix];
            hx = halo0 ? v.x : v.y;
        }
    }

    const int si = ty + 1, sj0 = 2*tx + 1, sj1 = sj0 + 1;

    // ---- noise: pixel 0 (+ halo ch0 lane) ----
    float y00, y01, yi0n[3];
    {
        uint32_t ce[6], rb[6];
        ce[0] = (uint32_t)(base_b + pix0);
#pragma unroll
        for (int i = 1; i < 5; i++) ce[i] = ce[0] + (uint32_t)(i*HW);
        ce[5] = hbase;
        if (halo0) tf_bitsN<6>(k0, k1, ce, rb);
        else       tf_bitsN<5>(k0, k1, ce, rb);
        y00 = noised_clip(xf0x, jax_normal(rb[0]));
        y01 = noised_clip(xf0y, jax_normal(rb[1]));
#pragma unroll
        for (int c = 0; c < 3; c++) yi0n[c] = noised_clip(xi0[c], jax_normal(rb[2+c]));
        sft[si][sj0] = make_float2(y00*80.0f, y01*80.0f);
        if (halo0)
            sft[hh+1][ww+1].x = hval ? noised_clip(hx, jax_normal(rb[5]))*80.0f : 0.0f;
    }

    // ---- noise: pixel 1 (+ halo ch1 lane) ----
    float y10, y11, yi1n[3];
    {
        uint32_t ce[6], rb[6];
        ce[0] = (uint32_t)(base_b + pix0 + 1);
#pragma unroll
        for (int i = 1; i < 5; i++) ce[i] = ce[0] + (uint32_t)(i*HW);
        ce[5] = hbase + (uint32_t)HW;
        if (halo1) tf_bitsN<6>(k0, k1, ce, rb);
        else       tf_bitsN<5>(k0, k1, ce, rb);
        y10 = noised_clip(xf1x, jax_normal(rb[0]));
        y11 = noised_clip(xf1y, jax_normal(rb[1]));
#pragma unroll
        for (int c = 0; c < 3; c++) yi1n[c] = noised_clip(xi1[c], jax_normal(rb[2+c]));
        sft[si][sj1] = make_float2(y10*80.0f, y11*80.0f);
        if (halo1)
            sft[hh+1][ww+1].y = hval ? noised_clip(hx, jax_normal(rb[5]))*80.0f : 0.0f;
    }
    __syncthreads();

    const float K0h = g_K[0], K1 = g_K[1];

    // ---- image channels: local data-term gradient, both pixels ----
    float oi0[3], oi1[3];
    {
        float jv0[3] = { j0.x, j0.y, j0.z };
        float d0[3], A0 = 0.0f;
#pragma unroll
        for (int c = 0; c < 3; c++) { d0[c] = fmaf(0.5f, yi0n[c], jv0[c]); A0 += d0[c]*d0[c]; }
        float cD0 = K0h * rsqrtf(A0 + 1e-5f);
#pragma unroll
        for (int c = 0; c < 3; c++) {
            float g = fminf(fmaxf(cD0 * d0[c], -0.03f), 0.03f);
            oi0[c] = fminf(fmaxf(fmaf(-10.0f, g, yi0n[c]), -1.0f), 1.0f);
        }
        float jv1[3] = { j1.x, j1.y, j1.z };
        float d1[3], A1 = 0.0f;
#pragma unroll
        for (int c = 0; c < 3; c++) { d1[c] = fmaf(0.5f, yi1n[c], jv1[c]); A1 += d1[c]*d1[c]; }
        float cD1 = K0h * rsqrtf(A1 + 1e-5f);
#pragma unroll
        for (int c = 0; c < 3; c++) {
            float g = fminf(fmaxf(cD1 * d1[c], -0.03f), 0.03f);
            oi1[c] = fminf(fmaxf(fmaf(-10.0f, g, yi1n[c]), -1.0f), 1.0f);
        }
    }

    // ---- flow channels: smoothness stencil, both pixels ----
    float of0x, of0y, of1x, of1y;
    {
        const bool hp = (h < Hh-1), hm = (h > 0);
        const bool wm0 = (c0 > 0);            // p0: wp always true
        const bool wp1 = (c0 < Ww-2);         // p1: wm always true

        float f0x = y00*80.0f, f0y = y01*80.0f;
        float f1x = y10*80.0f, f1y = y11*80.0f;

        float2 tl0  = sft[si][sj0-1];
        float2 tr1  = sft[si][sj1+1];
        float2 td0  = sft[si+1][sj0];
        float2 td1  = sft[si+1][sj1];
        float2 tdl0 = sft[si+1][sj0-1];
        float2 tu0  = sft[si-1][sj0];
        float2 tu1  = sft[si-1][sj1];
        float2 tur1 = sft[si-1][sj1+1];

        // R at p0 (shared: it is also p1's left-R)
        float dx0x = f1x - f0x,   dx0y = f1y - f0y;
        float dy0x = td0.x - f0x, dy0y = td0.y - f0y;
        float Sc0 = (dx0x*dx0x + dx0y*dx0y)
                  + (hp ? dy0x*dy0x + dy0y*dy0y : 0.0f) + 1e-5f;
        float gc0 = K1 * rsqrtf(Sc0);

        // R at p0's left (h, c0-1)
        float dxlx = f0x - tl0.x,    dxly = f0y - tl0.y;
        float dylx = tdl0.x - tl0.x, dyly = tdl0.y - tl0.y;
        float Sl0 = (dxlx*dxlx + dxly*dxly)
                  + (hp ? dylx*dylx + dyly*dyly : 0.0f) + 1e-5f;
        float gl0 = K1 * rsqrtf(Sl0);

        // R at p0's up (h-1, c0)
        float dxux = tu1.x - tu0.x, dxuy = tu1.y - tu0.y;
        float dyux = f0x - tu0.x,   dyuy = f0y - tu0.y;
        float Su0 = (dxux*dxux + dxuy*dxuy)           // wp0 true
                  + (dyux*dyux + dyuy*dyuy) + 1e-5f;
        float gu0 = K1 * rsqrtf(Su0);

        float g0x = -gc0*dx0x, g0y = -gc0*dx0y;       // wp0 true
        if (hp)  { g0x -= gc0*dy0x; g0y -= gc0*dy0y; }
        if (wm0) { g0x += gl0*dxlx; g0y += gl0*dxly; }
        if (hm)  { g0x += gu0*dyux; g0y += gu0*dyuy; }
        g0x = __fmul_rn(g0x, 80.0f);
        g0y = __fmul_rn(g0y, 80.0f);
        g0x = fminf(fmaxf(g0x, -0.03f), 0.03f);
        g0y = fminf(fmaxf(g0y, -0.03f), 0.03f);
        of0x = fminf(fmaxf(fmaf(-10.0f, g0x, y00), -1.0f), 1.0f);
        of0y = fminf(fmaxf(fmaf(-10.0f, g0y, y01), -1.0f), 1.0f);

        // R at p1
        float dx1x = tr1.x - f1x, dx1y = tr1.y - f1y;
        float dy1x = td1.x - f1x, dy1y = td1.y - f1y;
        float Sc1 = (wp1 ? dx1x*dx1x + dx1y*dx1y : 0.0f)
                  + (hp ? dy1x*dy1x + dy1y*dy1y : 0.0f) + 1e-5f;
        float gc1 = K1 * rsqrtf(Sc1);

        // R at p1's up (h-1, c0+1)
        float dxu1x = tur1.x - tu1.x, dxu1y = tur1.y - tu1.y;
        float dyu1x = f1x - tu1.x,    dyu1y = f1y - tu1.y;
        float Su1 = (wp1 ? dxu1x*dxu1x + dxu1y*dxu1y : 0.0f)
                  + (dyu1x*dyu1x + dyu1y*dyu1y) + 1e-5f;
        float gu1 = K1 * rsqrtf(Su1);

        float g1x = 0.0f, g1y = 0.0f;
        if (wp1) { g1x -= gc1*dx1x; g1y -= gc1*dx1y; }
        if (hp)  { g1x -= gc1*dy1x; g1y -= gc1*dy1y; }
        g1x += gc0*dx0x; g1y += gc0*dx0y;             // wm1 true; left-R == Sc0
        if (hm)  { g1x += gu1*dyu1x; g1y += gu1*dyu1y; }
        g1x = __fmul_rn(g1x, 80.0f);
        g1y = __fmul_rn(g1y, 80.0f);
        g1x = fminf(fmaxf(g1x, -0.03f), 0.03f);
        g1y = fminf(fmaxf(g1y, -0.03f), 0.03f);
        of1x = fminf(fmaxf(fmaf(-10.0f, g1x, y10), -1.0f), 1.0f);
        of1y = fminf(fmaxf(fmaf(-10.0f, g1y, y11), -1.0f), 1.0f);
    }

    // ---- vector stores ----
    *reinterpret_cast<float4*>(dstf + bpix0) = make_float4(of0x, of0y, of1x, of1y);
    dsti[bpix0]   = make_float4(oi0[0], oi0[1], oi0[2], 0.0f);
    dsti[bpix0+1] = make_float4(oi1[0], oi1[1], oi1[2], 0.0f);
}

// ---------------- energies: stage 1 (per-block partials) ----------------
__global__ void __launch_bounds__(256)
energy_partial(const float2* __restrict__ buff, const float4* __restrict__ bufi,
               const float* __restrict__ target1, const float* __restrict__ input1,
               const float* __restrict__ input2)
{
    const int mode = blockIdx.z, b = blockIdx.y, blk = blockIdx.x;
    const int t = threadIdx.x;
    const int PPB = HW / EBLK;   // 2048
    float sd = 0.0f, ss = 0.0f;

    for (int i = t; i < PPB; i += 256) {
        int pix = blk*PPB + i;
        int h = pix / Ww, w = pix - h*Ww;
        int bpix = b*HW + pix;

        float A = 0.0f;
        float4 vi = bufi[bpix];
        float iv[3] = { vi.x, vi.y, vi.z };
#pragma unroll
        for (int c = 0; c < 3; c++) {
            float i2    = input2[(b*3+c)*HW + pix];
            float img2p = ((i2*2.0f - 1.0f) + 1.0f) * 0.5f;
            float img1p;
            if (mode == 0) {
                float i1 = input1[(b*3+c)*HW + pix];
                img1p = ((i1*2.0f - 1.0f) + 1.0f) * 0.5f;
            } else {
                img1p = (iv[c] + 1.0f) * 0.5f;
            }
            float d = img1p - img2p;
            A += d*d;
        }
        sd += sqrtf(A + 1e-5f);

        float Bx = 0.0f, By = 0.0f;
#pragma unroll
        for (int c = 0; c < 2; c++) {
            float f, fr = 0.0f, fd = 0.0f;
            if (mode == 0) {
                const float* tp = target1 + (b*2+c)*HW;
                f = (tp[pix] / 80.0f) * 80.0f;
                if (w < Ww-1) fr = (tp[pix+1]  / 80.0f) * 80.0f;
                if (h < Hh-1) fd = (tp[pix+Ww] / 80.0f) * 80.0f;
            } else {
                f = (c ? buff[bpix].y : buff[bpix].x) * 80.0f;
                if (w < Ww-1) fr = (c ? buff[bpix+1].y  : buff[bpix+1].x)  * 80.0f;
                if (h < Hh-1) fd = (c ? buff[bpix+Ww].y : buff[bpix+Ww].x) * 80.0f;
            }
            if (w < Ww-1) { float dx = fr - f; Bx += dx*dx; }
            if (h < Hh-1) { float dy = fd - f; By += dy*dy; }
        }
        ss += sqrtf(Bx + By + 1e-5f);
    }

    __shared__ float rd[256], rs[256];
    rd[t] = sd; rs[t] = ss;
    __syncthreads();
    for (int s = 128; s > 0; s >>= 1) {
        if (t < s) { rd[t] += rd[t+s]; rs[t] += rs[t+s]; }
        __syncthreads();
    }
    if (t == 0) {
        int o = (mode*Bb + b)*EBLK + blk;
        g_part[2*o]   = rd[0];
        g_part[2*o+1] = rs[0];
    }
}

// ---------------- energies: stage 2 ----------------
__global__ void energy_final(const float* __restrict__ lw, float* __restrict__ out)
{
    int t = threadIdx.x;
    if (t >= 16) return;
    float sd = 0.0f, ss = 0.0f;
    for (int k = 0; k < EBLK; k++) {
        sd += g_part[2*(t*EBLK + k)];
        ss += g_part[2*(t*EBLK + k) + 1];
    }
    out[t] = (expf(lw[0])*sd + expf(lw[1])*ss) / 196608.0f;
}

// ---------------- output formatting ----------------
__global__ void __launch_bounds__(512)
format_kernel(const float2* __restrict__ buff, const float4* __restrict__ bufi,
              float* __restrict__ out)
{
    int i = blockIdx.x*512 + threadIdx.x;   // over Bb*HW pixels
    if (i >= Bb*HW) return;
    int b = i / HW;
    int pix = i - b*HW;
    float2 vf = buff[i];
    float4 vi = bufi[i];
    out[16 + (b*2 + 0)*HW + pix] = vf.x * 80.0f;
    out[16 + (b*2 + 1)*HW + pix] = vf.y * 80.0f;
    out[16 + Bb*2*HW + (b*3 + 0)*HW + pix] = (vi.x + 1.0f) * 0.5f;
    out[16 + Bb*2*HW + (b*3 + 1)*HW + pix] = (vi.y + 1.0f) * 0.5f;
    out[16 + Bb*2*HW + (b*3 + 2)*HW + pix] = (vi.z + 1.0f) * 0.5f;
}

// ---------------- host threefry (per-step keys) ----------------
static inline uint32_t h_rotl(uint32_t x, int d) { return (x << d) | (x >> (32 - d)); }
static void h_tf(uint32_t k0, uint32_t k1, uint32_t c0, uint32_t c1,
                 uint32_t& o0, uint32_t& o1)
{
    uint32_t ks2 = k0 ^ k1 ^ 0x1BD11BDAu;
    uint32_t x0 = c0 + k0, x1 = c1 + k1;
#define HR(r) { x0 += x1; x1 = h_rotl(x1, r); x1 ^= x0; }
    HR(13) HR(15) HR(26) HR(6)
    x0 += k1;  x1 += ks2 + 1u;
    HR(17) HR(29) HR(16) HR(24)
    x0 += ks2; x1 += k0 + 2u;
    HR(13) HR(15) HR(26) HR(6)
    x0 += k0;  x1 += k1 + 3u;
    HR(17) HR(29) HR(16) HR(24)
    x0 += k1;  x1 += ks2 + 4u;
    HR(13) HR(15) HR(26) HR(6)
    x0 += ks2; x1 += k0 + 5u;
#undef HR
    o0 = x0; o1 = x1;
}

extern "C" void kernel_launch(void* const* d_in, const int* in_sizes, int n_in,
                              void* d_out, int out_size)
{
    const float* target1 = (const float*)d_in[0];
    const float* input1  = (const float*)d_in[1];
    const float* input2  = (const float*)d_in[2];
    const float* init    = (const float*)d_in[3];
    const float* lw      = (const float*)d_in[4];
    float* out = (float*)d_out;

    float2 *fA, *fB; float4 *iA, *iB;
    cudaGetSymbolAddress((void**)&fA, g_flowA);
    cudaGetSymbolAddress((void**)&fB, g_flowB);
    cudaGetSymbolAddress((void**)&iA, g_imgA);
    cudaGetSymbolAddress((void**)&iB, g_imgB);

    k_init<<<1, 1>>>(lw);
    prep_j<<<(NIMG + 511)/512, 512>>>(input2);

    dim3 grid(Ww/32, Hh/32, Bb);   // (16, 12, 8)

    // step 0: planar src (init) -> split buffers A
    {
        uint32_t o0, o1;
        h_tf(0u, 1u, 0u, 0u, o0, o1);
        step_kernel<true><<<grid, 512>>>(init, nullptr, nullptr, fA, iA, o0, o1);
    }
    const float2* cf = fA; const float4* ci = iA;
    for (int t = 1; t < NSTEPS; t++) {
        uint32_t o0, o1;
        h_tf(0u, 1u, 0u, (uint32_t)t, o0, o1);
        float2* df = (t & 1) ? fB : fA;
        float4* di = (t & 1) ? iB : iA;
        step_kernel<false><<<grid, 512>>>(nullptr, cf, ci, df, di, o0, o1);
        cf = df; ci = di;
    }

    energy_partial<<<dim3(EBLK, Bb, 2), 256>>>(cf, ci, target1, input1, input2);
    energy_final<<<1, 32>>>(lw, out);
    format_kernel<<<(Bb*HW + 511)/512, 512>>>(cf, ci, out);
}

// round 17
// speedup vs baseline: 1.0524x; 1.0524x over previous
#include <cuda_runtime.h>
#include <cstdint>

#define Hh 384
#define Ww 512
#define Bb 8
#define HW (Hh*Ww)              // 196608
#define NIMG  (Bb*3*HW)         // 4718592
#define NSTEPS 200
#define TW 32
#define TH 16
#define EBLK 96

// ---------------- static scratch (no allocation allowed) ----------------
__device__ float2 g_flowA[Bb*HW];
__device__ float2 g_flowB[Bb*HW];
__device__ float4 g_imgA[Bb*HW];          // .xyz used
__device__ float4 g_imgB[Bb*HW];
__device__ float4 g_j[Bb*HW];             // j_c = 0.5 - img2p_c  (.xyz used)
__device__ float  g_K[2];                 // K0/2, K1  (pre-divided by H*W)
__device__ float  g_part[2*Bb*EBLK*2];

// ---------------- threefry2x32, JAX-exact, c0 = 0, N independent lanes ----
template<int N>
__device__ __forceinline__ void tf_bitsN(uint32_t k0, uint32_t k1,
                                         const uint32_t* c, uint32_t* r)
{
    const uint32_t ks2 = k0 ^ k1 ^ 0x1BD11BDAu;
    uint32_t x0[N], x1[N];
#pragma unroll
    for (int i = 0; i < N; i++) { x0[i] = k0; x1[i] = c[i] + k1; }

    auto rnd = [&](int rot) {
#pragma unroll
        for (int i = 0; i < N; i++) {
            x0[i] += x1[i];
            x1[i] = __funnelshift_l(x1[i], x1[i], rot);
            x1[i] ^= x0[i];
        }
    };
    auto inj = [&](uint32_t i0, uint32_t i1) {
#pragma unroll
        for (int i = 0; i < N; i++) { x0[i] += i0; x1[i] += i1; }
    };

    rnd(13); rnd(15); rnd(26); rnd(6);  inj(k1,  ks2 + 1u);
    rnd(17); rnd(29); rnd(16); rnd(24); inj(ks2, k0  + 2u);
    rnd(13); rnd(15); rnd(26); rnd(6);  inj(k0,  k1  + 3u);
    rnd(17); rnd(29); rnd(16); rnd(24); inj(k1,  ks2 + 4u);
    rnd(13); rnd(15); rnd(26); rnd(6);  inj(ks2, k0  + 5u);

#pragma unroll
    for (int i = 0; i < N; i++) r[i] = x0[i] ^ x1[i];
}

// ------------- jax.random.normal: uniform(lo,1) -> sqrt(2)*erfinv --------
__device__ __forceinline__ float jax_normal(uint32_t bits)
{
    const float lo = __uint_as_float(0xBF7FFFFFu);      // nextafter(-1, 0)
    float f = __uint_as_float((bits >> 9) | 0x3F800000u) - 1.0f;  // [0,1)
    float u = fmaxf(lo, f * 2.0f + lo);

    float w = -__logf(fmaf(-u, u, 1.0f));
    float p;
    if (w < 5.0f) {
        w = w - 2.5f;
        p =          2.81022636e-08f;
        p = p * w +  3.43273939e-07f;
        p = p * w + -3.5233877e-06f;
        p = p * w + -4.39150654e-06f;
        p = p * w +  0.00021858087f;
        p = p * w + -0.00125372503f;
        p = p * w + -0.00417768164f;
        p = p * w +  0.246640727f;
        p = p * w +  1.50140941f;
    } else {
        w = sqrtf(w) - 3.0f;
        p =         -0.000200214257f;
        p = p * w +  0.000100950558f;
        p = p * w +  0.00134934322f;
        p = p * w + -0.00367342844f;
        p = p * w +  0.00573950773f;
        p = p * w + -0.0076224613f;
        p = p * w +  0.00943887047f;
        p = p * w +  1.00167406f;
        p = p * w +  2.83297682f;
    }
    return 1.41421356237309515f * (p * u);
}

__device__ __forceinline__ float noised_clip(float x, float n)
{
    return fminf(fmaxf(fmaf(0.05f, n, x), -1.0f), 1.0f);
}

// ---------------- one-time prep: K and j ----------------
__global__ void k_init(const float* __restrict__ lw)
{
    g_K[0] = 0.5f * expf(lw[0]) / 196608.0f;   // K0/2
    g_K[1] = expf(lw[1]) / 196608.0f;          // K1 (0.5 and x2 cancel)
}

__global__ void __launch_bounds__(512)
prep_j(const float* __restrict__ input2)
{
    int i = blockIdx.x*512 + threadIdx.x;
    if (i >= NIMG) return;
    int b   = i / (3*HW);
    int r   = i - b*3*HW;
    int c   = r / HW;
    int pix = r - c*HW;
    float i2   = input2[i];
    float i2p  = ((i2*2.0f - 1.0f) + 1.0f) * 0.5f;
    reinterpret_cast<float*>(&g_j[b*HW + pix])[c] = 0.5f - i2p;
}

// ---------------- fused Langevin step: noise + analytic grad + update ----
// 1 px/thread (32x16 tile). Halo: 100 cells x 2 ch = 200 lanes, spread over
// 224 threads (7 full warps) as lane-6 of the interior threefry (ILP-hidden).
// tids 200..223 recompute duplicate lanes (benign identical smem writes).
template<bool SRC_PLANAR>
__global__ void __launch_bounds__(TW*TH, 3)
step_kernel(const float* __restrict__ srcp,
            const float2* __restrict__ srcf, const float4* __restrict__ srci,
            float2* __restrict__ dstf, float4* __restrict__ dsti,
            uint32_t k0, uint32_t k1)
{
    __shared__ float2 sft[TH+2][TW+2];     // SCALED (x80) noised flow, 1-halo

    const int b  = blockIdx.z;
    const int h0 = blockIdx.y * TH;
    const int w0 = blockIdx.x * TW;
    const int tid = threadIdx.x;
    const int tx = tid & (TW-1), ty = tid >> 5;
    const int base_b = b * 5 * HW;

    const int h = h0 + ty, w = w0 + tx;
    const int pix  = h*Ww + w;
    const int bpix = b*HW + pix;

    // ---- halo duty (warp-uniform split at 7 warps) ----
    const bool hduty = (tid < 224);
    int cidx = tid;                         // cell index 0..99 (mod 100)
    if (cidx >= 200) cidx -= 200; else if (cidx >= 100) cidx -= 100;
    const int ch = (tid >= 100 && tid < 200) ? 1 : 0;
    int hh, ww;
    if (cidx < (TW+2))           { hh = -1; ww = cidx - 1; }
    else if (cidx < 2*(TW+2))    { hh = TH; ww = cidx - (TW+2) - 1; }
    else if (cidx < 2*(TW+2)+TH) { hh = cidx - 2*(TW+2); ww = -1; }
    else                         { hh = cidx - (2*(TW+2)+TH); ww = TW; }
    const int hg = h0 + hh, wg = w0 + ww;
    const bool hval = ((unsigned)hg < (unsigned)Hh) && ((unsigned)wg < (unsigned)Ww);
    const int hpix = hg*Ww + wg;
    const uint32_t he = (uint32_t)(base_b + hpix) + (ch ? (uint32_t)HW : 0u);

    // ---- counters = JAX planar flat indices ----
    uint32_t ce[6];
    ce[0] = (uint32_t)(base_b + pix);
#pragma unroll
    for (int i = 1; i < 5; i++) ce[i] = ce[0] + (uint32_t)(i*HW);
    ce[5] = he;

    // ---- front-batched loads ----
    float xv[5];
    if (SRC_PLANAR) {
#pragma unroll
        for (int i = 0; i < 5; i++) xv[i] = srcp[ce[i]];
    } else {
        float2 vf = srcf[bpix];
        float4 vi = srci[bpix];
        xv[0] = vf.x; xv[1] = vf.y; xv[2] = vi.x; xv[3] = vi.y; xv[4] = vi.z;
    }
    float4 j4 = g_j[bpix];

    float hx = 0.0f;
    if (hduty && hval) {
        if (SRC_PLANAR) hx = srcp[he];
        else {
            float2 v2 = srcf[b*HW + hpix];
            hx = ch ? v2.y : v2.x;
        }
    }

    // ---- threefry: 5 interior lanes (+1 halo lane for 7 warps) ----
    uint32_t rb[6];
    if (hduty) tf_bitsN<6>(k0, k1, ce, rb);
    else       tf_bitsN<5>(k0, k1, ce, rb);

    float y0 = noised_clip(xv[0], jax_normal(rb[0]));
    float y1 = noised_clip(xv[1], jax_normal(rb[1]));
    float f0 = y0*80.0f, f1 = y1*80.0f;
    sft[ty+1][tx+1] = make_float2(f0, f1);

    if (hduty) {
        float z = hval ? noised_clip(hx, jax_normal(rb[5])) * 80.0f : 0.0f;
        reinterpret_cast<float*>(&sft[hh+1][ww+1])[ch] = z;
    }
    __syncthreads();

    const float K0h = g_K[0], K1 = g_K[1];

    // ---- image channels: local data-term gradient ----
    float oi0, oi1, oi2;
    {
        float jv[3] = { j4.x, j4.y, j4.z };
        float yimg[3], diff[3], A = 0.0f;
#pragma unroll
        for (int c = 0; c < 3; c++) {
            float y = noised_clip(xv[2+c], jax_normal(rb[2+c]));
            yimg[c] = y;
            float d = fmaf(0.5f, y, jv[c]);     // (y+1)/2 - img2p
            diff[c] = d;
            A += d*d;
        }
        float cD = K0h * rsqrtf(A + 1e-5f);
        float o[3];
#pragma unroll
        for (int c = 0; c < 3; c++) {
            float g = cD * diff[c];
            g = fminf(fmaxf(g, -0.03f), 0.03f);
            o[c] = fminf(fmaxf(fmaf(-10.0f, g, yimg[c]), -1.0f), 1.0f);
        }
        oi0 = o[0]; oi1 = o[1]; oi2 = o[2];
    }

    // ---- flow channels: smoothness-term stencil gradient ----
    float of0, of1;
    {
        const int si = ty + 1, sj = tx + 1;
        const bool wp = (w < Ww-1), hp = (h < Hh-1);
        const bool wm = (w > 0),    hm = (h > 0);

        float2 tr  = sft[si][sj+1];     // taps already x80
        float2 td  = sft[si+1][sj];
        float2 tl  = sft[si][sj-1];
        float2 tu  = sft[si-1][sj];
        float2 tdl = sft[si+1][sj-1];
        float2 tur = sft[si-1][sj+1];

        // R at (h, w)
        float dx0 = tr.x - f0, dx1 = tr.y - f1;
        float dy0 = td.x - f0, dy1 = td.y - f1;
        float Sc = (wp ? dx0*dx0 + dx1*dx1 : 0.0f)
                 + (hp ? dy0*dy0 + dy1*dy1 : 0.0f) + 1e-5f;
        float gAc = K1 * rsqrtf(Sc);            // = 2*K1*(0.5/sqrt)

        // R at (h, w-1)
        float dxl0 = f0 - tl.x,    dxl1 = f1 - tl.y;
        float dyl0 = tdl.x - tl.x, dyl1 = tdl.y - tl.y;
        float Sl = (dxl0*dxl0 + dxl1*dxl1)
                 + (hp ? dyl0*dyl0 + dyl1*dyl1 : 0.0f) + 1e-5f;
        float gAl = K1 * rsqrtf(Sl);

        // R at (h-1, w)
        float dxu0 = tur.x - tu.x, dxu1 = tur.y - tu.y;
        float dyu0 = f0 - tu.x,    dyu1 = f1 - tu.y;
        float Su = (wp ? dxu0*dxu0 + dxu1*dxu1 : 0.0f)
                 + (dyu0*dyu0 + dyu1*dyu1) + 1e-5f;
        float gAu = K1 * rsqrtf(Su);

        float g0 = 0.0f, g1 = 0.0f;
        if (wp) { g0 -= gAc*dx0;  g1 -= gAc*dx1;  }
        if (hp) { g0 -= gAc*dy0;  g1 -= gAc*dy1;  }
        if (wm) { g0 += gAl*dxl0; g1 += gAl*dxl1; }
        if (hm) { g0 += gAu*dyu0; g1 += gAu*dyu1; }
        g0 = __fmul_rn(g0, 80.0f);
        g1 = __fmul_rn(g1, 80.0f);
        g0 = fminf(fmaxf(g0, -0.03f), 0.03f);
        g1 = fminf(fmaxf(g1, -0.03f), 0.03f);

        of0 = fminf(fmaxf(fmaf(-10.0f, g0, y0), -1.0f), 1.0f);
        of1 = fminf(fmaxf(fmaf(-10.0f, g1, y1), -1.0f), 1.0f);
    }

    // ---- vector stores ----
    dstf[bpix] = make_float2(of0, of1);
    dsti[bpix] = make_float4(oi0, oi1, oi2, 0.0f);
}

// ---------------- energies: stage 1 (per-block partials) ----------------
__global__ void __launch_bounds__(256)
energy_partial(const float2* __restrict__ buff, const float4* __restrict__ bufi,
               const float* __restrict__ target1, const float* __restrict__ input1,
               const float* __restrict__ input2)
{
    const int mode = blockIdx.z, b = blockIdx.y, blk = blockIdx.x;
    const int t = threadIdx.x;
    const int PPB = HW / EBLK;   // 2048
    float sd = 0.0f, ss = 0.0f;

    for (int i = t; i < PPB; i += 256) {
        int pix = blk*PPB + i;
        int h = pix / Ww, w = pix - h*Ww;
        int bpix = b*HW + pix;

        float A = 0.0f;
        float4 vi = bufi[bpix];
        float iv[3] = { vi.x, vi.y, vi.z };
#pragma unroll
        for (int c = 0; c < 3; c++) {
            float i2    = input2[(b*3+c)*HW + pix];
            float img2p = ((i2*2.0f - 1.0f) + 1.0f) * 0.5f;
            float img1p;
            if (mode == 0) {
                float i1 = input1[(b*3+c)*HW + pix];
                img1p = ((i1*2.0f - 1.0f) + 1.0f) * 0.5f;
            } else {
                img1p = (iv[c] + 1.0f) * 0.5f;
            }
            float d = img1p - img2p;
            A += d*d;
        }
        sd += sqrtf(A + 1e-5f);

        float Bx = 0.0f, By = 0.0f;
#pragma unroll
        for (int c = 0; c < 2; c++) {
            float f, fr = 0.0f, fd = 0.0f;
            if (mode == 0) {
                const float* tp = target1 + (b*2+c)*HW;
                f = (tp[pix] / 80.0f) * 80.0f;
                if (w < Ww-1) fr = (tp[pix+1]  / 80.0f) * 80.0f;
                if (h < Hh-1) fd = (tp[pix+Ww] / 80.0f) * 80.0f;
            } else {
                f = (c ? buff[bpix].y : buff[bpix].x) * 80.0f;
                if (w < Ww-1) fr = (c ? buff[bpix+1].y  : buff[bpix+1].x)  * 80.0f;
                if (h < Hh-1) fd = (c ? buff[bpix+Ww].y : buff[bpix+Ww].x) * 80.0f;
            }
            if (w < Ww-1) { float dx = fr - f; Bx += dx*dx; }
            if (h < Hh-1) { float dy = fd - f; By += dy*dy; }
        }
        ss += sqrtf(Bx + By + 1e-5f);
    }

    __shared__ float rd[256], rs[256];
    rd[t] = sd; rs[t] = ss;
    __syncthreads();
    for (int s = 128; s > 0; s >>= 1) {
        if (t < s) { rd[t] += rd[t+s]; rs[t] += rs[t+s]; }
        __syncthreads();
    }
    if (t == 0) {
        int o = (mode*Bb + b)*EBLK + blk;
        g_part[2*o]   = rd[0];
        g_part[2*o+1] = rs[0];
    }
}

// ---------------- energies: stage 2 ----------------
__global__ void energy_final(const float* __restrict__ lw, float* __restrict__ out)
{
    int t = threadIdx.x;
    if (t >= 16) return;
    float sd = 0.0f, ss = 0.0f;
    for (int k = 0; k < EBLK; k++) {
        sd += g_part[2*(t*EBLK + k)];
        ss += g_part[2*(t*EBLK + k) + 1];
    }
    out[t] = (expf(lw[0])*sd + expf(lw[1])*ss) / 196608.0f;
}

// ---------------- output formatting ----------------
__global__ void __launch_bounds__(512)
format_kernel(const float2* __restrict__ buff, const float4* __restrict__ bufi,
              float* __restrict__ out)
{
    int i = blockIdx.x*512 + threadIdx.x;   // over Bb*HW pixels
    if (i >= Bb*HW) return;
    int b = i / HW;
    int pix = i - b*HW;
    float2 vf = buff[i];
    float4 vi = bufi[i];
    out[16 + (b*2 + 0)*HW + pix] = vf.x * 80.0f;
    out[16 + (b*2 + 1)*HW + pix] = vf.y * 80.0f;
    out[16 + Bb*2*HW + (b*3 + 0)*HW + pix] = (vi.x + 1.0f) * 0.5f;
    out[16 + Bb*2*HW + (b*3 + 1)*HW + pix] = (vi.y + 1.0f) * 0.5f;
    out[16 + Bb*2*HW + (b*3 + 2)*HW + pix] = (vi.z + 1.0f) * 0.5f;
}

// ---------------- host threefry (per-step keys) ----------------
static inline uint32_t h_rotl(uint32_t x, int d) { return (x << d) | (x >> (32 - d)); }
static void h_tf(uint32_t k0, uint32_t k1, uint32_t c0, uint32_t c1,
                 uint32_t& o0, uint32_t& o1)
{
    uint32_t ks2 = k0 ^ k1 ^ 0x1BD11BDAu;
    uint32_t x0 = c0 + k0, x1 = c1 + k1;
#define HR(r) { x0 += x1; x1 = h_rotl(x1, r); x1 ^= x0; }
    HR(13) HR(15) HR(26) HR(6)
    x0 += k1;  x1 += ks2 + 1u;
    HR(17) HR(29) HR(16) HR(24)
    x0 += ks2; x1 += k0 + 2u;
    HR(13) HR(15) HR(26) HR(6)
    x0 += k0;  x1 += k1 + 3u;
    HR(17) HR(29) HR(16) HR(24)
    x0 += k1;  x1 += ks2 + 4u;
    HR(13) HR(15) HR(26) HR(6)
    x0 += ks2; x1 += k0 + 5u;
#undef HR
    o0 = x0; o1 = x1;
}

extern "C" void kernel_launch(void* const* d_in, const int* in_sizes, int n_in,
                              void* d_out, int out_size)
{
    const float* target1 = (const float*)d_in[0];
    const float* input1  = (const float*)d_in[1];
    const float* input2  = (const float*)d_in[2];
    const float* init    = (const float*)d_in[3];
    const float* lw      = (const float*)d_in[4];
    float* out = (float*)d_out;

    float2 *fA, *fB; float4 *iA, *iB;
    cudaGetSymbolAddress((void**)&fA, g_flowA);
    cudaGetSymbolAddress((void**)&fB, g_flowB);
    cudaGetSymbolAddress((void**)&iA, g_imgA);
    cudaGetSymbolAddress((void**)&iB, g_imgB);

    k_init<<<1, 1>>>(lw);
    prep_j<<<(NIMG + 511)/512, 512>>>(input2);

    dim3 grid(Ww/TW, Hh/TH, Bb);   // (16, 24, 8)

    // step 0: planar src (init) -> split buffers A
    {
        uint32_t o0, o1;
        h_tf(0u, 1u, 0u, 0u, o0, o1);
        step_kernel<true><<<grid, TW*TH>>>(init, nullptr, nullptr, fA, iA, o0, o1);
    }
    const float2* cf = fA; const float4* ci = iA;
    for (int t = 1; t < NSTEPS; t++) {
        uint32_t o0, o1;
        h_tf(0u, 1u, 0u, (uint32_t)t, o0, o1);
        float2* df = (t & 1) ? fB : fA;
        float4* di = (t & 1) ? iB : iA;
        step_kernel<false><<<grid, TW*TH>>>(nullptr, cf, ci, df, di, o0, o1);
        cf = df; ci = di;
    }

    energy_partial<<<dim3(EBLK, Bb, 2), 256>>>(cf, ci, target1, input1, input2);
    energy_final<<<1, 32>>>(lw, out);
    format_kernel<<<(Bb*HW + 511)/512, 512>>>(cf, ci, out);
}